// round 17
// baseline (speedup 1.0000x reference)
#include <cuda_runtime.h>
#include <cstdint>

// WanRotaryPosEmbedS2VStyle: build (freqs_cos, freqs_sin) grids.
//
//   output: cos (1, n_tok, 1, 128) then sin; n_tok = F*3600.
//   Per token (f,y,x): ch [0,44)=t_tab[pt], [44,86)=h_tab[y], [86,128)=w_tab[x].
//
// R17: R16 locked the optimum (bench 14.816, ncu 14.368). Final probe: the
// only untested lever is store cache policy. Same exact structure as R3/R16
// but stores use st.global.cs.v4.f32 (cache-streaming, evict-first) — the
// output is a pure write stream rewritten every replay, so L2 allocation/
// eviction policy is the one thing the SM-side experiments never touched.
// If neutral, R16's kernel stands as final.

#define T_DIM 44
#define H_DIM 42
#define W_DIM 42
#define GRID_W 60
#define GRID_HW 3600
#define FIXED_REF 30
#define X_PER 4            // tokens per warp (divides 60) — measured optimum

__device__ __forceinline__ void stg_cs4(float* p, float a, float b, float c, float d)
{
    asm volatile("st.global.cs.v4.f32 [%0], {%1, %2, %3, %4};"
                 :: "l"(p), "f"(a), "f"(b), "f"(c), "f"(d) : "memory");
}

__global__ void wan_rope_kernel(
    const float* __restrict__ tcos, const float* __restrict__ hcos,
    const float* __restrict__ wcos, const float* __restrict__ tsin,
    const float* __restrict__ hsin, const float* __restrict__ wsin,
    const int*   __restrict__ nvf_p,
    float* __restrict__ out, int n_tok, int n_warps)
{
    const int gtid = blockIdx.x * blockDim.x + threadIdx.x;
    const int w    = gtid >> 5;
    if (w >= n_warps) return;
    const int lane = gtid & 31;
    const int d0   = lane << 2;            // channels [d0, d0+4)

    const int tok0 = w * X_PER;            // X_PER tokens, same (f,y) row
    const int f    = tok0 / GRID_HW;
    const int rem  = tok0 - f * GRID_HW;
    const int y    = rem / GRID_W;

    const int video_pp = __ldg(nvf_p);
    const int pt = (f < video_pp) ? f : FIXED_REF;

    const int tbase = pt * T_DIM;
    const int hbase = y * H_DIM - T_DIM;
    const int wbase = (rem - y * GRID_W) * W_DIM - (T_DIM + H_DIM);

    const float* pc[2];
    const float* ps[2];
    bool   isw[2];
    float2 c[2], s[2];
#pragma unroll
    for (int h = 0; h < 2; h++) {
        const int d = d0 + 2 * h;          // even; pair (d,d+1) in one table
        if (d < T_DIM)              { pc[h] = tcos + tbase + d; ps[h] = tsin + tbase + d; isw[h] = false; }
        else if (d < T_DIM + H_DIM) { pc[h] = hcos + hbase + d; ps[h] = hsin + hbase + d; isw[h] = false; }
        else                        { pc[h] = wcos + wbase + d; ps[h] = wsin + wbase + d; isw[h] = true;  }
        c[h] = __ldg(reinterpret_cast<const float2*>(pc[h]));
        s[h] = __ldg(reinterpret_cast<const float2*>(ps[h]));
    }

    float* oc = out + (size_t)tok0 * 128 + d0;
    float* os = oc + (size_t)n_tok * 128;

#pragma unroll
    for (int xi = 0; xi < X_PER; xi++) {
        if (xi) {
#pragma unroll
            for (int h = 0; h < 2; h++) {
                if (isw[h]) {              // predicated: only w-lanes reload
                    pc[h] += W_DIM;  ps[h] += W_DIM;
                    c[h] = __ldg(reinterpret_cast<const float2*>(pc[h]));
                    s[h] = __ldg(reinterpret_cast<const float2*>(ps[h]));
                }
            }
        }
        stg_cs4(oc, c[0].x, c[0].y, c[1].x, c[1].y);
        stg_cs4(os, s[0].x, s[0].y, s[1].x, s[1].y);
        oc += 128;  os += 128;
    }
}

extern "C" void kernel_launch(void* const* d_in, const int* in_sizes, int n_in,
                              void* d_out, int out_size)
{
    // 0: hidden_states (unused)
    // 1: freq_t_cos  2: freq_h_cos  3: freq_w_cos
    // 4: freq_t_sin  5: freq_h_sin  6: freq_w_sin
    // 7: num_video_frames (int32)   8: num_ref_frames (int32)
    const float* tcos = (const float*)d_in[1];
    const float* hcos = (const float*)d_in[2];
    const float* wcos = (const float*)d_in[3];
    const float* tsin = (const float*)d_in[4];
    const float* hsin = (const float*)d_in[5];
    const float* wsin = (const float*)d_in[6];
    const int*   nvf  = (const int*)d_in[7];

    float* out = (float*)d_out;

    const int n_tok   = out_size / 256;    // out_size = 2 * n_tok * 128
    const int n_warps = n_tok / X_PER;     // n_tok = F*3600, divisible by X_PER
    const int threads = 256;
    const int blocks  = (n_warps * 32 + threads - 1) / threads;

    wan_rope_kernel<<<blocks, threads>>>(tcos, hcos, wcos, tsin, hsin, wsin,
                                         nvf, out, n_tok, n_warps);
}